// round 3
// baseline (speedup 1.0000x reference)
#include <cuda_runtime.h>
#include <cuda_bf16.h>

// out[n,h,d] = sum_j x[n,j,d] * FM[j+1,h] * Agg[0,j,h]
// (reference's sort/gap/code machinery telescopes to this linear map)
//
// R2: Little's-law fix — 8 explicitly-batched float4 loads per thread
// (4 KB/warp, whole 4 MB input outstanding), 2-way j-split + 1 shfl_xor.

#define S_DIM 16
#define H_DIM 4
#define N_DIM 128
#define D_DIM 512

__global__ void __launch_bounds__(128) cie_linear_kernel(
    const float* __restrict__ x,     // (N, S, D)
    const float* __restrict__ FM,    // (S+1, H)
    const float* __restrict__ Agg,   // (1, S, H)
    float* __restrict__ out)         // (N, H, D)
{
    __shared__ float W[S_DIM][H_DIM];
    const int tid = threadIdx.x;
    if (tid < S_DIM * H_DIM) {
        int j = tid / H_DIM, h = tid % H_DIM;
        W[j][h] = FM[(j + 1) * H_DIM + h] * Agg[j * H_DIM + h];
    }
    __syncthreads();

    const int n     = blockIdx.x >> 1;
    const int dhalf = blockIdx.x & 1;
    const int col   = tid >> 1;        // 0..63 local d4 column
    const int jg    = tid & 1;         // j-half: j = jg*8 .. jg*8+7
    const int d4    = dhalf * 64 + col;

    const float4* xp = reinterpret_cast<const float4*>(
        x + (size_t)n * S_DIM * D_DIM) + d4;

    // Batch ALL 8 loads before any FMA -> 8 outstanding LDG.128 per thread.
    float4 v[8];
#pragma unroll
    for (int jj = 0; jj < 8; jj++)
        v[jj] = xp[(jg * 8 + jj) * (D_DIM / 4)];

    float4 acc[H_DIM];
#pragma unroll
    for (int h = 0; h < H_DIM; h++) acc[h] = make_float4(0.f, 0.f, 0.f, 0.f);

#pragma unroll
    for (int jj = 0; jj < 8; jj++) {
        const int j = jg * 8 + jj;
#pragma unroll
        for (int h = 0; h < H_DIM; h++) {
            const float w = W[j][h];
            acc[h].x = fmaf(v[jj].x, w, acc[h].x);
            acc[h].y = fmaf(v[jj].y, w, acc[h].y);
            acc[h].z = fmaf(v[jj].z, w, acc[h].z);
            acc[h].w = fmaf(v[jj].w, w, acc[h].w);
        }
    }

    // Combine the two j-halves (adjacent lanes).
#pragma unroll
    for (int h = 0; h < H_DIM; h++) {
        acc[h].x += __shfl_xor_sync(0xffffffffu, acc[h].x, 1);
        acc[h].y += __shfl_xor_sync(0xffffffffu, acc[h].y, 1);
        acc[h].z += __shfl_xor_sync(0xffffffffu, acc[h].z, 1);
        acc[h].w += __shfl_xor_sync(0xffffffffu, acc[h].w, 1);
    }

    if (jg == 0) {
        float4* op = reinterpret_cast<float4*>(
            out + (size_t)n * H_DIM * D_DIM) + d4;
#pragma unroll
        for (int h = 0; h < H_DIM; h++) op[h * (D_DIM / 4)] = acc[h];
    }
}

extern "C" void kernel_launch(void* const* d_in, const int* in_sizes, int n_in,
                              void* d_out, int out_size) {
    const float* x   = (const float*)d_in[0];   // (128,16,512) f32
    const float* FM  = (const float*)d_in[1];   // (17,4) f32
    const float* Agg = (const float*)d_in[2];   // (1,16,4) f32
    // d_in[3] = source_index, unused: the table gather telescopes away.
    float* out = (float*)d_out;                 // (128,4,512) f32

    cie_linear_kernel<<<N_DIM * 2, 128>>>(x, FM, Agg, out);
}